// round 7
// baseline (speedup 1.0000x reference)
#include <cuda_runtime.h>
#include <cstdint>

#define NJ   17
#define NP   14
#define NB   256
#define NCH  59                 // 17 + 3*14
#define NGRP 20                 // 14 HEM pair-blocks + 6 L2D triple-blocks
#define NBLK (NGRP * NB)        // 5120 blocks

#define CHUNK_BYTES  8192       // 8 KB = 2048 floats = 32 heatmap rows
#define CHUNK_F4     512
#define NSTAGE       3

__constant__ int c_par[NP] = {0,1,2,0,4,5,0,8,14,15,8,11,12,8};
__constant__ int c_chi[NP] = {1,2,3,4,5,6,8,14,15,16,11,12,13,10};

// Per-channel partial sums, indexed [b*NCH + ch]. All valid slots written every launch.
__device__ float        g_part[NB * NCH];
__device__ unsigned int g_count;   // zero at module load; last block resets each call

// ---------------- PTX helpers ----------------
static __device__ __forceinline__ uint32_t s2u(const void* p) {
    uint32_t a;
    asm("{ .reg .u64 t; cvta.to.shared.u64 t, %1; cvt.u32.u64 %0, t; }" : "=r"(a) : "l"(p));
    return a;
}
static __device__ __forceinline__ void mbar_init(uint32_t m, uint32_t cnt) {
    asm volatile("mbarrier.init.shared.b64 [%0], %1;" :: "r"(m), "r"(cnt) : "memory");
}
static __device__ __forceinline__ void mbar_expect(uint32_t m, uint32_t bytes) {
    asm volatile("mbarrier.arrive.expect_tx.shared.b64 _, [%0], %1;" :: "r"(m), "r"(bytes) : "memory");
}
static __device__ __forceinline__ void mbar_wait(uint32_t m, uint32_t ph) {
    asm volatile(
        "{\n\t.reg .pred P1;\n"
        "LW%=:\n\tmbarrier.try_wait.parity.acquire.cta.shared::cta.b64 P1, [%0], %1, 0x989680;\n"
        "\t@P1 bra LD%=;\n\tbra LW%=;\n"
        "LD%=:\n\t}"
        :: "r"(m), "r"(ph) : "memory");
}
static __device__ __forceinline__ void bulk_g2s(uint32_t dst, const void* src,
                                                uint32_t bytes, uint32_t mbar) {
    asm volatile(
        "cp.async.bulk.shared::cta.global.mbarrier::complete_tx::bytes [%0], [%1], %2, [%3];"
        :: "r"(dst), "l"(src), "r"(bytes), "r"(mbar) : "memory");
}
static __device__ __forceinline__ void fence_async() {
    asm volatile("fence.proxy.async.shared::cta;" ::: "memory");
}

// max over integer grid i in [0,63] of exp(-(i-x)^2/4): nearest grid point.
__device__ __forceinline__ float gmax1d(float x) {
    float i = fminf(fmaxf(rintf(x), 0.f), 63.f);
    float d = i - x;
    return __expf(-d * d * 0.25f);
}

__device__ __forceinline__ float blockReduce256(float v, float* red, int tid) {
    #pragma unroll
    for (int o = 16; o > 0; o >>= 1) v += __shfl_down_sync(0xffffffffu, v, o);
    if ((tid & 31) == 0) red[tid >> 5] = v;
    __syncthreads();
    v = (tid < 8) ? red[tid] : 0.f;
    if (tid < 32) {
        #pragma unroll
        for (int o = 4; o > 0; o >>= 1) v += __shfl_down_sync(0xffffffffu, v, o);
    }
    return v;   // valid on tid 0
}

__global__ void __launch_bounds__(256, 8)
k_fused(const float* __restrict__ mo,
        const float* __restrict__ joints,
        const float* __restrict__ j2d,
        const float* __restrict__ pred,
        float* __restrict__ out) {
    __shared__ __align__(128) float buf[NSTAGE][CHUNK_F4 * 4];   // 3 x 8KB
    __shared__ __align__(16)  float tab[6][64];
    __shared__ __align__(8)   unsigned long long mbar_store[NSTAGE];
    __shared__ float red[8];
    __shared__ int   s_last;

    const int bx  = blockIdx.x;          // 0..13 HEM pair, 14..19 L2D triple
    const int b   = blockIdx.y;
    const int tid = threadIdx.x;
    const bool isHem = (bx < NP);

    int   ch0;
    int   nch = 3;
    float w0 = 0.f, w1 = 0.f, w2 = 0.f;   // HEM: weight of hc per local channel

    const uint32_t mb = s2u(mbar_store);
    if (tid == 0) {
        mbar_init(mb + 0, 1);
        mbar_init(mb + 8, 1);
        mbar_init(mb + 16, 1);
    }

    // ---- channel decode + table build (as R5) ----
    if (isHem) {
        const int pr = bx;
        ch0 = NJ + 3 * pr;
        const int pj = c_par[pr], cj = c_chi[pr];
        const float xp = j2d[(b * NJ + pj) * 2 + 0] * 64.f;
        const float yp = j2d[(b * NJ + pj) * 2 + 1] * 64.f;
        const float xc = j2d[(b * NJ + cj) * 2 + 0] * 64.f;
        const float yc = j2d[(b * NJ + cj) * 2 + 1] * 64.f;
        const float invp = 1.f / (gmax1d(xp) * gmax1d(yp));
        const float invc = 1.f / (gmax1d(xc) * gmax1d(yc));
        const float dz = joints[(b * NJ + pj) * 3 + 2] - joints[(b * NJ + cj) * 3 + 2];
        const int r = (dz > 0.1f) ? 1 : ((fabsf(dz) < 0.1f) ? 0 : -1);
        w0 = (r == -1) ? 1.f : 0.f;
        w1 = (r ==  0) ? 1.f : 0.f;
        w2 = (r ==  1) ? 1.f : 0.f;
        const int t = tid >> 6, g = tid & 63;
        const float fg = (float)g;
        if      (t == 0) { float d = fg - xp; tab[0][g] = expf(-d * d * 0.25f) * invp; }
        else if (t == 1) { float d = fg - yp; tab[1][g] = expf(-d * d * 0.25f); }
        else if (t == 2) { float d = fg - xc; tab[2][g] = expf(-d * d * 0.25f) * invc; }
        else             { float d = fg - yc; tab[3][g] = expf(-d * d * 0.25f); }
    } else {
        const int grp = bx - NP;           // 0..5
        ch0 = 3 * grp;
        if (grp == 5) nch = 2;
        const int t = tid >> 6, g = tid & 63;
        const float fg = (float)g;
        {
            const int c = t >> 1;
            const int j = ch0 + c;
            const float x = j2d[(b * NJ + j) * 2 + 0] * 64.f;
            const float y = j2d[(b * NJ + j) * 2 + 1] * 64.f;
            if ((t & 1) == 0) {
                float inv = 1.f / (gmax1d(x) * gmax1d(y));
                float d = fg - x; tab[2 * c][g] = expf(-d * d * 0.25f) * inv;
            } else {
                float d = fg - y; tab[2 * c + 1][g] = expf(-d * d * 0.25f);
            }
        }
        if (nch == 3 && tid < 128) {
            const int j = ch0 + 2;
            const float x = j2d[(b * NJ + j) * 2 + 0] * 64.f;
            const float y = j2d[(b * NJ + j) * 2 + 1] * 64.f;
            if (t == 0) {
                float inv = 1.f / (gmax1d(x) * gmax1d(y));
                float d = fg - x; tab[4][g] = expf(-d * d * 0.25f) * inv;
            } else {
                float d = fg - y; tab[5][g] = expf(-d * d * 0.25f);
            }
        }
    }
    __syncthreads();   // mbar init + tables visible

    // ---- TMA pipeline over tot chunks of 8KB ----
    const char* src = (const char*)(mo + (((size_t)b * NCH + ch0) << 12));
    const int tot = 2 * nch;               // 6 (or 4 for last L2D group)

    if (tid == 0) {
        #pragma unroll
        for (int s = 0; s < NSTAGE; s++) {
            if (s < tot) {
                mbar_expect(mb + 8 * s, CHUNK_BYTES);
                bulk_g2s(s2u(buf[s]), src + (size_t)s * CHUNK_BYTES, CHUNK_BYTES, mb + 8 * s);
            }
        }
    }

    float acc0 = 0.f, acc1 = 0.f, acc2 = 0.f;
    for (int c = 0; c < tot; c++) {
        const int st = (c >= NSTAGE) ? c - NSTAGE : c;   // c % 3 for c < 6
        mbar_wait(mb + 8 * st, (c >= NSTAGE) ? 1u : 0u);

        const int lc = c >> 1;       // local channel 0..2
        const int h  = c & 1;        // which 32-row half
        const float4* bp = (const float4*)buf[st];
        float la = 0.f;

        if (isHem) {
            const float wp = (lc == 1) ? 1.f : 0.f;
            const float wc = (lc == 0) ? w0 : ((lc == 1) ? w1 : w2);
            #pragma unroll
            for (int j = 0; j < 2; j++) {
                const int e4 = tid + j * 256;
                float4 m = bp[e4];
                const int gi = h * 32 + (e4 >> 4);
                const int k4 = e4 & 15;
                const float  hpx = tab[0][gi];
                const float  hcx = tab[2][gi];
                const float4 vp  = ((const float4*)tab[1])[k4];
                const float4 vc  = ((const float4*)tab[3])[k4];
                #pragma unroll
                for (int n = 0; n < 4; n++) {
                    float d = fmaf(-wc, hcx * (&vc.x)[n],
                              fmaf(-wp, hpx * (&vp.x)[n], (&m.x)[n]));
                    la = fmaf(d, d, la);
                }
            }
        } else {
            #pragma unroll
            for (int j = 0; j < 2; j++) {
                const int e4 = tid + j * 256;
                float4 m = bp[e4];
                const int gi = h * 32 + (e4 >> 4);
                const int k4 = e4 & 15;
                const float  sx = tab[2 * lc][gi];
                const float4 v  = ((const float4*)tab[2 * lc + 1])[k4];
                #pragma unroll
                for (int n = 0; n < 4; n++) {
                    float d = fmaf(-sx, (&v.x)[n], (&m.x)[n]);
                    la = fmaf(d, d, la);
                }
            }
        }
        if      (lc == 0) acc0 += la;
        else if (lc == 1) acc1 += la;
        else              acc2 += la;

        __syncthreads();   // everyone done reading buf[st]
        if (tid == 0 && c + NSTAGE < tot) {
            fence_async();
            mbar_expect(mb + 8 * st, CHUNK_BYTES);
            bulk_g2s(s2u(buf[st]), src + (size_t)(c + NSTAGE) * CHUNK_BYTES,
                     CHUNK_BYTES, mb + 8 * st);
        }
    }

    // ---- per-channel block reductions ----
    float S0 = blockReduce256(acc0, red, tid);
    __syncthreads();
    float S1 = blockReduce256(acc1, red, tid);
    __syncthreads();
    float S2 = blockReduce256(acc2, red, tid);

    // ---- publish, detect last block ----
    if (tid == 0) {
        float* dst = &g_part[b * NCH + ch0];
        dst[0] = S0;
        dst[1] = S1;
        if (nch == 3) dst[2] = S2;
        __threadfence();
        unsigned int prev = atomicAdd(&g_count, 1u);
        s_last = (prev == (unsigned)(NBLK - 1)) ? 1 : 0;
    }
    __syncthreads();
    if (!s_last) return;

    // ---- last block: combine. thread tid = batch tid ----
    const float* pp = g_part + tid * NCH;
    float l2d = 0.f;
    #pragma unroll
    for (int c = 0; c < NJ; c++) l2d += __ldcg(&pp[c]);
    float hem = 0.f;
    #pragma unroll
    for (int pr = 0; pr < NP; pr++) {
        float s0 = __ldcg(&pp[NJ + 3 * pr + 0]);
        float s1 = __ldcg(&pp[NJ + 3 * pr + 1]);
        float s2 = __ldcg(&pp[NJ + 3 * pr + 2]);
        float t = sqrtf(s0) + sqrtf(s1) + sqrtf(s2);
        hem += t * t;
    }

    float l = 0.f;
    const float* jb = joints + tid * NJ * 3;
    const float* pb = pred   + tid * NJ * 3;
    #pragma unroll
    for (int i = 0; i < NJ * 3; i++) l += fabsf(jb[i] - pb[i]);

    float v = l + 0.005f * (l2d + hem);
    __syncthreads();
    float tot2 = blockReduce256(v, red, tid);
    if (tid == 0) {
        out[0] = tot2 * (1.f / 256.f);
        g_count = 0;
    }
}

extern "C" void kernel_launch(void* const* d_in, const int* in_sizes, int n_in,
                              void* d_out, int out_size) {
    const float* pred   = (const float*)d_in[0];
    const float* joints = (const float*)d_in[1];
    const float* mo     = (const float*)d_in[2];
    const float* j2d    = (const float*)d_in[3];
    float* out = (float*)d_out;

    k_fused<<<dim3(NGRP, NB), 256>>>(mo, joints, j2d, pred, out);
}

// round 8
// speedup vs baseline: 1.5520x; 1.5520x over previous
#include <cuda_runtime.h>

#define NJ   17
#define NP   14
#define NB   256
#define NCH  59                 // 17 + 3*14
#define NGRP 20                 // 14 HEM pair-blocks + 6 L2D triple-blocks
#define NBLK (NGRP * NB)        // 5120 blocks total

__constant__ int c_par[NP] = {0,1,2,0,4,5,0,8,14,15,8,11,12,8};
__constant__ int c_chi[NP] = {1,2,3,4,5,6,8,14,15,16,11,12,13,10};

// Per-channel partial sums, indexed [b*NCH + ch]. All valid slots written every launch.
__device__ float        g_part[NB * NCH];
__device__ unsigned int g_count;   // zero at module load; last block resets each call

// max over integer grid i in [0,63] of exp(-(i-x)^2/4): nearest grid point.
__device__ __forceinline__ float gmax1d(float x) {
    float i = fminf(fmaxf(rintf(x), 0.f), 63.f);
    float d = i - x;
    return __expf(-d * d * 0.25f);
}

__device__ __forceinline__ float blockReduce256(float v, float* red, int tid) {
    #pragma unroll
    for (int o = 16; o > 0; o >>= 1) v += __shfl_down_sync(0xffffffffu, v, o);
    if ((tid & 31) == 0) red[tid >> 5] = v;
    __syncthreads();
    v = (tid < 8) ? red[tid] : 0.f;
    if (tid < 32) {
        #pragma unroll
        for (int o = 4; o > 0; o >>= 1) v += __shfl_down_sync(0xffffffffu, v, o);
    }
    return v;   // valid on tid 0
}

__global__ void __launch_bounds__(256, 8)
k_fused(const float* __restrict__ mo,
        const float* __restrict__ joints,
        const float* __restrict__ j2d,
        const float* __restrict__ pred,
        float* __restrict__ out) {
    // 6 tables of 64 floats: [0]=exA [1]=eyA [2]=exB [3]=eyB [4]=exC [5]=eyC
    __shared__ __align__(16) float tab[6][64];
    __shared__ float red[8];
    __shared__ int   s_last;

    const int bx  = blockIdx.x;          // 0..13 HEM pair, 14..19 L2D triple
    const int b   = blockIdx.y;
    const int tid = threadIdx.x;
    const bool isHem = (bx < NP);

    int   ch0;                  // first canonical channel of this block
    int   nch = 3;              // channels handled (2 for last L2D group)
    float w0 = 0.f, w1 = 0.f, w2 = 0.f;   // HEM: weight of hc in each channel

    if (isHem) {
        const int pr = bx;
        ch0 = NJ + 3 * pr;
        const int pj = c_par[pr], cj = c_chi[pr];
        const float xp = j2d[(b * NJ + pj) * 2 + 0] * 64.f;
        const float yp = j2d[(b * NJ + pj) * 2 + 1] * 64.f;
        const float xc = j2d[(b * NJ + cj) * 2 + 0] * 64.f;
        const float yc = j2d[(b * NJ + cj) * 2 + 1] * 64.f;
        const float invp = 1.f / (gmax1d(xp) * gmax1d(yp));
        const float invc = 1.f / (gmax1d(xc) * gmax1d(yc));
        const float dz = joints[(b * NJ + pj) * 3 + 2] - joints[(b * NJ + cj) * 3 + 2];
        const int r = (dz > 0.1f) ? 1 : ((fabsf(dz) < 0.1f) ? 0 : -1);
        w0 = (r == -1) ? 1.f : 0.f;
        w1 = (r ==  0) ? 1.f : 0.f;
        w2 = (r ==  1) ? 1.f : 0.f;
        const int t = tid >> 6, g = tid & 63;
        const float fg = (float)g;
        if      (t == 0) { float d = fg - xp; tab[0][g] = expf(-d * d * 0.25f) * invp; }
        else if (t == 1) { float d = fg - yp; tab[1][g] = expf(-d * d * 0.25f); }
        else if (t == 2) { float d = fg - xc; tab[2][g] = expf(-d * d * 0.25f) * invc; }
        else             { float d = fg - yc; tab[3][g] = expf(-d * d * 0.25f); }
    } else {
        const int grp = bx - NP;           // 0..5
        ch0 = 3 * grp;
        if (grp == 5) nch = 2;             // joints 15,16 only
        const int t = tid >> 6, g = tid & 63;
        const float fg = (float)g;
        {
            const int c = t >> 1;                 // 0 or 1
            const int j = ch0 + c;
            const float x = j2d[(b * NJ + j) * 2 + 0] * 64.f;
            const float y = j2d[(b * NJ + j) * 2 + 1] * 64.f;
            if ((t & 1) == 0) {
                float inv = 1.f / (gmax1d(x) * gmax1d(y));
                float d = fg - x; tab[2 * c][g] = expf(-d * d * 0.25f) * inv;
            } else {
                float d = fg - y; tab[2 * c + 1][g] = expf(-d * d * 0.25f);
            }
        }
        if (nch == 3 && tid < 128) {
            const int j = ch0 + 2;
            const float x = j2d[(b * NJ + j) * 2 + 0] * 64.f;
            const float y = j2d[(b * NJ + j) * 2 + 1] * 64.f;
            if (t == 0) {
                float inv = 1.f / (gmax1d(x) * gmax1d(y));
                float d = fg - x; tab[4][g] = expf(-d * d * 0.25f) * inv;
            } else {
                float d = fg - y; tab[5][g] = expf(-d * d * 0.25f);
            }
        }
    }
    __syncthreads();

    // ---- stream 3 channels x 16KB (plain LDG.128) ----
    const float4* p = (const float4*)(mo + (((size_t)b * NCH + ch0) << 12));
    float a0 = 0.f, a1 = 0.f, a2 = 0.f;
    const float4* eyA4 = (const float4*)tab[1];
    const float4* eyB4 = (const float4*)tab[3];
    const float4* eyC4 = (const float4*)tab[5];

    if (isHem) {
        const float nw0 = -w0, nw1 = -w1, nw2 = -w2;
        #pragma unroll
        for (int it = 0; it < 4; it++) {
            const int e4 = tid + it * 256;
            float4 m0 = p[e4];
            float4 m1 = p[e4 + 1024];
            float4 m2 = p[e4 + 2048];
            const int i  = e4 >> 4;
            const int k4 = e4 & 15;
            const float aP = tab[0][i];
            const float aB = tab[2][i];
            const float4 vP = eyA4[k4];
            const float4 vB = eyB4[k4];
            #pragma unroll
            for (int n = 0; n < 4; n++) {
                const float mp = (&m0.x)[n], mm = (&m1.x)[n], mc = (&m2.x)[n];
                const float hp = aP * (&vP.x)[n];
                const float hc = aB * (&vB.x)[n];
                float d0 = fmaf(nw0, hc, mp);                 // m0 - w0*hc
                float d1 = fmaf(nw1, hc, mm - hp);            // m1 - hp - w1*hc
                float d2 = fmaf(nw2, hc, mc);                 // m2 - w2*hc
                a0 = fmaf(d0, d0, a0);
                a1 = fmaf(d1, d1, a1);
                a2 = fmaf(d2, d2, a2);
            }
        }
    } else {
        const bool n3 = (nch == 3);
        #pragma unroll
        for (int it = 0; it < 4; it++) {
            const int e4 = tid + it * 256;
            float4 m0 = p[e4];
            float4 m1 = p[e4 + 1024];
            float4 m2;
            if (n3) m2 = p[e4 + 2048];
            const int i  = e4 >> 4;
            const int k4 = e4 & 15;
            const float s0 = tab[0][i];
            const float s1 = tab[2][i];
            const float s2 = n3 ? tab[4][i] : 0.f;
            const float4 v0 = eyA4[k4];
            const float4 v1 = eyB4[k4];
            const float4 v2 = n3 ? eyC4[k4] : make_float4(0.f, 0.f, 0.f, 0.f);
            #pragma unroll
            for (int n = 0; n < 4; n++) {
                float d0 = fmaf(-s0, (&v0.x)[n], (&m0.x)[n]);
                float d1 = fmaf(-s1, (&v1.x)[n], (&m1.x)[n]);
                a0 = fmaf(d0, d0, a0);
                a1 = fmaf(d1, d1, a1);
                if (n3) {
                    float d2 = fmaf(-s2, (&v2.x)[n], (&m2.x)[n]);
                    a2 = fmaf(d2, d2, a2);
                }
            }
        }
    }

    // ---- per-channel block reductions ----
    float S0 = blockReduce256(a0, red, tid);
    __syncthreads();
    float S1 = blockReduce256(a1, red, tid);
    __syncthreads();
    float S2 = blockReduce256(a2, red, tid);

    // ---- publish, detect last block ----
    if (tid == 0) {
        float* dst = &g_part[b * NCH + ch0];
        dst[0] = S0;
        dst[1] = S1;
        if (nch == 3) dst[2] = S2;
        __threadfence();
        unsigned int prev = atomicAdd(&g_count, 1u);
        s_last = (prev == (unsigned)(NBLK - 1)) ? 1 : 0;
    }
    __syncthreads();
    if (!s_last) return;

    // ---- last block: combine. thread tid = batch tid ----
    const float* pp = g_part + tid * NCH;
    float l2d = 0.f;
    #pragma unroll
    for (int c = 0; c < NJ; c++) l2d += __ldcg(&pp[c]);
    float hem = 0.f;
    #pragma unroll
    for (int pr = 0; pr < NP; pr++) {
        float s0 = __ldcg(&pp[NJ + 3 * pr + 0]);
        float s1 = __ldcg(&pp[NJ + 3 * pr + 1]);
        float s2 = __ldcg(&pp[NJ + 3 * pr + 2]);
        float t = sqrtf(s0) + sqrtf(s1) + sqrtf(s2);
        hem += t * t;
    }

    // l3d: 51 abs-diffs for batch tid
    float l = 0.f;
    const float* jb = joints + tid * NJ * 3;
    const float* pb = pred   + tid * NJ * 3;
    #pragma unroll
    for (int i = 0; i < NJ * 3; i++) l += fabsf(jb[i] - pb[i]);

    float v = l + 0.005f * (l2d + hem);
    __syncthreads();   // red[] reuse
    float tot = blockReduce256(v, red, tid);
    if (tid == 0) {
        out[0] = tot * (1.f / 256.f);
        g_count = 0;   // reset for next graph replay
    }
}

extern "C" void kernel_launch(void* const* d_in, const int* in_sizes, int n_in,
                              void* d_out, int out_size) {
    const float* pred   = (const float*)d_in[0];
    const float* joints = (const float*)d_in[1];
    const float* mo     = (const float*)d_in[2];
    const float* j2d    = (const float*)d_in[3];
    float* out = (float*)d_out;

    k_fused<<<dim3(NGRP, NB), 256>>>(mo, joints, j2d, pred, out);
}

// round 9
// speedup vs baseline: 1.9208x; 1.2376x over previous
#include <cuda_runtime.h>

#define NJ   17
#define NP   14
#define NB   256
#define NCH  59            // 17 + 3*14
#define GX   (NJ + NP)     // 31 block columns

__constant__ int c_par[NP] = {0,1,2,0,4,5,0,8,14,15,8,11,12,8};
__constant__ int c_chi[NP] = {1,2,3,4,5,6,8,14,15,16,11,12,13,10};

// Per-column accumulators. Zero at module load; k_final re-zeroes after reading,
// so every launch (correctness run + each graph replay) starts from zero.
__device__ double g_slot[GX];

// max of exp(-(i-x)^2/4) over integer grid i in [0,63]: nearest grid point.
__device__ __forceinline__ float gmax1d(float x) {
    float i = fminf(fmaxf(rintf(x), 0.f), 63.f);
    float d = i - x;
    return __expf(-d * d * 0.25f);
}

__device__ __forceinline__ float blockReduce256(float v, float* red, int tid) {
    #pragma unroll
    for (int o = 16; o > 0; o >>= 1) v += __shfl_down_sync(0xffffffffu, v, o);
    if ((tid & 31) == 0) red[tid >> 5] = v;
    __syncthreads();
    v = (tid < 8) ? red[tid] : 0.f;
    if (tid < 32) {
        #pragma unroll
        for (int o = 4; o > 0; o >>= 1) v += __shfl_down_sync(0xffffffffu, v, o);
    }
    return v;   // valid on tid 0
}

// ---------------- streaming kernel (R1/R6-style loop, natural regs) ----------------
__global__ void k_main(const float* __restrict__ mo,
                       const float* __restrict__ joints,
                       const float* __restrict__ j2d) {
    __shared__ __align__(16) float ex[64], ey[64], ex2[64], ey2[64];
    __shared__ float red[8];

    const int b   = blockIdx.y;
    const int tid = threadIdx.x;

    const float4* ey4  = (const float4*)ey;
    const float4* ey24 = (const float4*)ey2;

    if (blockIdx.x < NJ) {
        // ---------------- L2D path ----------------
        const int j = blockIdx.x;
        const float x = j2d[(b * NJ + j) * 2 + 0] * 64.f;
        const float y = j2d[(b * NJ + j) * 2 + 1] * 64.f;
        const float inv = 1.f / (gmax1d(x) * gmax1d(y));
        if (tid < 64)       { float d = (float)tid - x;        ex[tid] = expf(-d * d * 0.25f) * inv; }
        else if (tid < 128) { int k = tid - 64; float d = (float)k - y; ey[k] = expf(-d * d * 0.25f); }
        __syncthreads();

        const float4* p = (const float4*)(mo + (((size_t)b * NCH + j) << 12));
        float acc = 0.f;
        #pragma unroll
        for (int it = 0; it < 4; it++) {
            int e4 = tid + it * 256;
            float4 m = p[e4];
            int i  = e4 >> 4;
            int k4 = e4 & 15;
            float  hx = ex[i];
            float4 v  = ey4[k4];
            float d0 = m.x - hx * v.x;
            float d1 = m.y - hx * v.y;
            float d2 = m.z - hx * v.z;
            float d3 = m.w - hx * v.w;
            acc += d0 * d0 + d1 * d1 + d2 * d2 + d3 * d3;
        }
        float S = blockReduce256(acc, red, tid);
        if (tid == 0) atomicAdd(&g_slot[blockIdx.x], (double)S);
    } else {
        // ---------------- HEM path ----------------
        const int pr = blockIdx.x - NJ;
        const int pj = c_par[pr], cj = c_chi[pr];
        const float xp = j2d[(b * NJ + pj) * 2 + 0] * 64.f;
        const float yp = j2d[(b * NJ + pj) * 2 + 1] * 64.f;
        const float xc = j2d[(b * NJ + cj) * 2 + 0] * 64.f;
        const float yc = j2d[(b * NJ + cj) * 2 + 1] * 64.f;
        const float invp = 1.f / (gmax1d(xp) * gmax1d(yp));
        const float invc = 1.f / (gmax1d(xc) * gmax1d(yc));
        if (tid < 64)       { float d = (float)tid - xp;         ex [tid] = expf(-d * d * 0.25f) * invp; }
        else if (tid < 128) { int k = tid - 64;  float d = (float)k - yp; ey [k] = expf(-d * d * 0.25f); }
        else if (tid < 192) { int k = tid - 128; float d = (float)k - xc; ex2[k] = expf(-d * d * 0.25f) * invc; }
        else                { int k = tid - 192; float d = (float)k - yc; ey2[k] = expf(-d * d * 0.25f); }
        __syncthreads();

        const float dz = joints[(b * NJ + pj) * 3 + 2] - joints[(b * NJ + cj) * 3 + 2];
        const int r = (dz > 0.1f) ? 1 : ((fabsf(dz) < 0.1f) ? 0 : -1);

        const float4* p0 = (const float4*)(mo + (((size_t)b * NCH + NJ + pr * 3) << 12));
        float a0 = 0.f, a1 = 0.f, a2 = 0.f;
        #pragma unroll
        for (int it = 0; it < 4; it++) {
            int e4 = tid + it * 256;
            int i  = e4 >> 4;
            int k4 = e4 & 15;
            float  hpx = ex[i];
            float  hcx = ex2[i];
            float4 vp  = ey4[k4];
            float4 vc  = ey24[k4];
            float m0[4], m1[4], m2[4];
            *(float4*)m0 = p0[e4];
            *(float4*)m1 = p0[e4 + 1024];
            *(float4*)m2 = p0[e4 + 2048];
            #pragma unroll
            for (int n = 0; n < 4; n++) {
                float hp = hpx * (&vp.x)[n];
                float hc = hcx * (&vc.x)[n];
                float t0 = (r == -1) ? hc : 0.f;
                float t1 = (r ==  0) ? (hp + hc) : hp;
                float t2 = (r ==  1) ? hc : 0.f;
                float d0 = t0 - m0[n];
                float d1 = t1 - m1[n];
                float d2 = t2 - m2[n];
                a0 += d0 * d0;
                a1 += d1 * d1;
                a2 += d2 * d2;
            }
        }
        float S0 = blockReduce256(a0, red, tid);
        __syncthreads();
        float S1 = blockReduce256(a1, red, tid);
        __syncthreads();
        float S2 = blockReduce256(a2, red, tid);
        if (tid == 0) {
            float s = sqrtf(S0) + sqrtf(S1) + sqrtf(S2);
            atomicAdd(&g_slot[blockIdx.x], (double)(s * s));
        }
    }
}

// ---------------- finalize: l3d + combine + reset ----------------
__global__ void k_final(const float* __restrict__ joints,
                        const float* __restrict__ pred,
                        float* __restrict__ out) {
    __shared__ float red[8];
    const int tid = threadIdx.x;

    // l3d: thread tid = batch tid (51 abs-diffs)
    float l = 0.f;
    const float* jb = joints + tid * NJ * 3;
    const float* pb = pred   + tid * NJ * 3;
    #pragma unroll
    for (int i = 0; i < NJ * 3; i++) l += fabsf(jb[i] - pb[i]);
    float ltot = blockReduce256(l, red, tid);

    if (tid == 0) {
        double s = 0.0;
        #pragma unroll
        for (int i = 0; i < GX; i++) s += g_slot[i];
        out[0] = (float)(((double)ltot + 0.005 * s) * (1.0 / 256.0));
    }
    __syncthreads();              // reads done before reset
    if (tid < GX) g_slot[tid] = 0.0;
}

extern "C" void kernel_launch(void* const* d_in, const int* in_sizes, int n_in,
                              void* d_out, int out_size) {
    const float* pred   = (const float*)d_in[0];
    const float* joints = (const float*)d_in[1];
    const float* mo     = (const float*)d_in[2];
    const float* j2d    = (const float*)d_in[3];
    float* out = (float*)d_out;

    k_main<<<dim3(GX, NB), 256>>>(mo, joints, j2d);
    k_final<<<1, 256>>>(joints, pred, out);
}